// round 1
// baseline (speedup 1.0000x reference)
#include <cuda_runtime.h>
#include <math.h>

// Problem constants
#define BB   4
#define TT   2048
#define DD   1024
#define HH   64
#define NSd  32
#define KK   8
#define HVd  32
#define NT   8192      // BB*TT tokens
#define NTS  65536     // NT*KK token-slots
#define MAXTILES 64    // up to 4096 tokens per head (expected ~1024)

// ---------------- scratch (static device memory; no allocation) ----------------
__device__ float g_ra[NT * 128];          // [token][0:64]=router logits, [64:128]=a
__device__ int   g_topi[NTS];             // selected head per (token,slot)
__device__ float g_rw[NTS];               // renormalized router weight
__device__ float g_dsel[NTS];             // decay per (token,slot)
__device__ int   g_count[HH];
__device__ int   g_offset[HH];
__device__ int   g_cursor[HH];
__device__ int   g_list[NTS];             // per-head token-slot lists
__device__ float g_qsel[NTS * 32];        // l2norm(silu(q)) * rw
__device__ float g_ksel[NTS * 32];        // l2norm(silu(k))
__device__ float g_vsel[NTS * 32];        // silu(v)
__device__ float g_yslot[NTS * 32];       // per-slot read output
__device__ float g_WoT[32 * DD];          // Wo transposed [v][d]

// ---------------- small helpers ----------------
__device__ __forceinline__ float silu_f(float x) {
    return x / (1.0f + expf(-x));
}

// ---------------- kernel: zero counters ----------------
__global__ void zero_counts() {
    int h = threadIdx.x;
    if (h < HH) { g_count[h] = 0; g_cursor[h] = 0; }
}

// ---------------- kernel: transpose Wo [DD][32] -> [32][DD] ----------------
__global__ void transpose_wo(const float* __restrict__ Wo) {
    int o = blockIdx.x * 256 + threadIdx.x;   // 0..32767
    int v = o >> 10, d = o & 1023;
    g_WoT[o] = Wo[d * 32 + v];
}

// ---------------- kernel: router + decay GEMM: g_ra = x @ [Wr;Wa]^T ----------------
// BM=64 tokens, BN=128 outputs, BK=16. 256 threads, each 8x4 outputs.
__global__ void gemm_ra(const float* __restrict__ x,
                        const float* __restrict__ Wr,
                        const float* __restrict__ Wa) {
    __shared__ __align__(16) float Xs[16][72];
    __shared__ __align__(16) float Ws[16][136];
    int tid = threadIdx.x;
    int m0 = blockIdx.x * 64;
    int ty = tid >> 5;          // 0..7 -> token rows ty*8..
    int tx = tid & 31;          // 0..31 -> col group tx*4..
    float acc[8][4];
#pragma unroll
    for (int i = 0; i < 8; i++)
#pragma unroll
        for (int j = 0; j < 4; j++) acc[i][j] = 0.0f;

    for (int k0 = 0; k0 < DD; k0 += 16) {
        // load X tile 64x16 (transposed into SMEM)
        {
            int r = tid >> 2, c4 = (tid & 3) * 4;
            const float4 v4 = *(const float4*)(x + (size_t)(m0 + r) * DD + k0 + c4);
            Xs[c4 + 0][r] = v4.x; Xs[c4 + 1][r] = v4.y;
            Xs[c4 + 2][r] = v4.z; Xs[c4 + 3][r] = v4.w;
        }
        // load W tile 128x16
#pragma unroll
        for (int uu = 0; uu < 2; uu++) {
            int u = tid + uu * 256;
            int r = u >> 2, c4 = (u & 3) * 4;
            const float* src = (r < 64) ? (Wr + (size_t)r * DD)
                                        : (Wa + (size_t)(r - 64) * DD);
            const float4 v4 = *(const float4*)(src + k0 + c4);
            Ws[c4 + 0][r] = v4.x; Ws[c4 + 1][r] = v4.y;
            Ws[c4 + 2][r] = v4.z; Ws[c4 + 3][r] = v4.w;
        }
        __syncthreads();
#pragma unroll
        for (int kk = 0; kk < 16; kk++) {
            float4 a0 = *(const float4*)&Xs[kk][ty * 8];
            float4 a1 = *(const float4*)&Xs[kk][ty * 8 + 4];
            float4 b4 = *(const float4*)&Ws[kk][tx * 4];
            float av[8] = {a0.x, a0.y, a0.z, a0.w, a1.x, a1.y, a1.z, a1.w};
            float bv[4] = {b4.x, b4.y, b4.z, b4.w};
#pragma unroll
            for (int i = 0; i < 8; i++)
#pragma unroll
                for (int j = 0; j < 4; j++)
                    acc[i][j] = fmaf(av[i], bv[j], acc[i][j]);
        }
        __syncthreads();
    }
#pragma unroll
    for (int i = 0; i < 8; i++)
#pragma unroll
        for (int j = 0; j < 4; j++)
            g_ra[(size_t)(m0 + ty * 8 + i) * 128 + tx * 4 + j] = acc[i][j];
}

// ---------------- kernel: routing (top-8, rw, decay) ----------------
__global__ void route_kernel(const float* __restrict__ A_log,
                             const float* __restrict__ dt_bias) {
    int lane = threadIdx.x & 31;
    int w = threadIdx.x >> 5;
    int tok = blockIdx.x * 8 + w;
    const float* ra = g_ra + (size_t)tok * 128;
    float v0 = ra[lane], v1 = ra[lane + 32];
    int i0 = lane, i1 = lane + 32;
    float topv[8]; int tophi[8];
#pragma unroll
    for (int it = 0; it < 8; it++) {
        float bv; int bi;
        if (v0 > v1 || (v0 == v1 && i0 < i1)) { bv = v0; bi = i0; }
        else                                  { bv = v1; bi = i1; }
#pragma unroll
        for (int off = 16; off > 0; off >>= 1) {
            float ov = __shfl_xor_sync(0xffffffffu, bv, off);
            int   oi = __shfl_xor_sync(0xffffffffu, bi, off);
            if (ov > bv || (ov == bv && oi < bi)) { bv = ov; bi = oi; }
        }
        topv[it] = bv; tophi[it] = bi;
        if (bi == i0) v0 = -INFINITY;
        if (bi == i1) v1 = -INFINITY;
    }
    // renormalized weights over the top-8 (softmax Z cancels)
    float s = 0.0f;
#pragma unroll
    for (int j = 0; j < 8; j++) s += expf(topv[j] - topv[0]);

    // pick this lane's slot (avoid dynamic-index spill)
    float myv = 0.0f; int myh = 0;
#pragma unroll
    for (int it = 0; it < 8; it++)
        if (lane == it) { myv = topv[it]; myh = tophi[it]; }

    if (lane < 8) {
        float rw = expf(myv - topv[0]) / s;
        float z = ra[64 + myh] + dt_bias[myh];
        float sp = (z > 20.0f) ? z : log1pf(expf(z));
        float dec = expf(-expf(A_log[myh]) * sp);
        int e = tok * 8 + lane;
        g_topi[e] = myh;
        g_rw[e] = rw;
        g_dsel[e] = dec;
        atomicAdd(&g_count[myh], 1);
    }
}

// ---------------- kernel: prefix sum over 64 head counts ----------------
__global__ void prefix_kernel() {
    if (threadIdx.x == 0) {
        int acc = 0;
        for (int h = 0; h < HH; h++) { g_offset[h] = acc; acc += g_count[h]; }
    }
}

// ---------------- kernel: scatter token-slots into per-head lists ----------------
__global__ void scatter_kernel() {
    int e = blockIdx.x * 256 + threadIdx.x;
    int h = g_topi[e];
    int pos = atomicAdd(&g_cursor[h], 1);
    g_list[g_offset[h] + pos] = e;
}

// ---------------- kernel: grouped q/k/v GEMM (selected heads only) ----------------
// For head h: C[64 tokens][96] = Xg[64][1024] * [Wq_h; Wk_h; Wv_h]^T (rows h*32..)
// Epilogue: silu + l2norm(q,k), silu(v), q scaled by rw. Compact output.
__global__ void gemm_qkv(const float* __restrict__ x,
                         const float* __restrict__ Wq,
                         const float* __restrict__ Wk,
                         const float* __restrict__ Wv) {
    __shared__ int s_ent[64];
    __shared__ __align__(16) float Xs[16][68];
    __shared__ __align__(16) float Ws[16][104];
    __shared__ __align__(16) float Cs[64][97];
    int tid = threadIdx.x;
    int h = blockIdx.y;
    int cnt = g_count[h];
    int t0 = blockIdx.x * 64;
    if (t0 >= cnt) return;
    int off = g_offset[h];
    if (tid < 64) s_ent[tid] = (t0 + tid < cnt) ? g_list[off + t0 + tid] : -1;
    __syncthreads();

    int ty = tid >> 4;   // 0..15 -> rows ty*4..
    int tx = tid & 15;   // 0..15 -> cols tx*6..
    float acc[4][6];
#pragma unroll
    for (int i = 0; i < 4; i++)
#pragma unroll
        for (int j = 0; j < 6; j++) acc[i][j] = 0.0f;

    for (int k0 = 0; k0 < DD; k0 += 16) {
        // gathered X tile 64x16
        {
            int r = tid >> 2, c4 = (tid & 3) * 4;
            int e = s_ent[r];
            float4 v4 = make_float4(0.f, 0.f, 0.f, 0.f);
            if (e >= 0)
                v4 = *(const float4*)(x + (size_t)(e >> 3) * DD + k0 + c4);
            Xs[c4 + 0][r] = v4.x; Xs[c4 + 1][r] = v4.y;
            Xs[c4 + 2][r] = v4.z; Xs[c4 + 3][r] = v4.w;
        }
        // W tile 96x16 (rows 0-31 Wq, 32-63 Wk, 64-95 Wv; 384 float4 loads)
        {
            int u = tid;
            int r = u >> 2, c4 = (u & 3) * 4;
            const float* src = (r < 32) ? (Wq + (size_t)(h * 32 + r) * DD)
                             : (r < 64) ? (Wk + (size_t)(h * 32 + r - 32) * DD)
                                        : (Wv + (size_t)(h * 32 + r - 64) * DD);
            const float4 v4 = *(const float4*)(src + k0 + c4);
            Ws[c4 + 0][r] = v4.x; Ws[c4 + 1][r] = v4.y;
            Ws[c4 + 2][r] = v4.z; Ws[c4 + 3][r] = v4.w;
        }
        if (tid < 128) {
            int u = tid + 256;
            int r = u >> 2, c4 = (u & 3) * 4;
            const float* src = (r < 64) ? (Wk + (size_t)(h * 32 + r - 32) * DD)
                                        : (Wv + (size_t)(h * 32 + r - 64) * DD);
            const float4 v4 = *(const float4*)(src + k0 + c4);
            Ws[c4 + 0][r] = v4.x; Ws[c4 + 1][r] = v4.y;
            Ws[c4 + 2][r] = v4.z; Ws[c4 + 3][r] = v4.w;
        }
        __syncthreads();
#pragma unroll
        for (int kk = 0; kk < 16; kk++) {
            float4 a4 = *(const float4*)&Xs[kk][ty * 4];
            float av[4] = {a4.x, a4.y, a4.z, a4.w};
            float bv[6];
#pragma unroll
            for (int j = 0; j < 6; j++) bv[j] = Ws[kk][tx * 6 + j];
#pragma unroll
            for (int i = 0; i < 4; i++)
#pragma unroll
                for (int j = 0; j < 6; j++)
                    acc[i][j] = fmaf(av[i], bv[j], acc[i][j]);
        }
        __syncthreads();
    }
#pragma unroll
    for (int i = 0; i < 4; i++)
#pragma unroll
        for (int j = 0; j < 6; j++)
            Cs[ty * 4 + i][tx * 6 + j] = acc[i][j];
    __syncthreads();

    int lane = tid & 31, w = tid >> 5;
#pragma unroll 1
    for (int rep = 0; rep < 8; rep++) {
        int r = rep * 8 + w;
        int e = s_ent[r];
        if (e < 0) continue;
        float wr = g_rw[e];
        // q: silu -> l2norm -> * rw
        float qv = Cs[r][lane];
        float qs = silu_f(qv);
        float ssq = qs * qs;
#pragma unroll
        for (int o = 16; o > 0; o >>= 1) ssq += __shfl_xor_sync(0xffffffffu, ssq, o);
        g_qsel[(size_t)e * 32 + lane] = qs * rsqrtf(ssq + 1e-6f) * wr;
        // k: silu -> l2norm
        float kv = Cs[r][32 + lane];
        float ks = silu_f(kv);
        float ssk = ks * ks;
#pragma unroll
        for (int o = 16; o > 0; o >>= 1) ssk += __shfl_xor_sync(0xffffffffu, ssk, o);
        g_ksel[(size_t)e * 32 + lane] = ks * rsqrtf(ssk + 1e-6f);
        // v: silu
        float vv = Cs[r][64 + lane];
        g_vsel[(size_t)e * 32 + lane] = silu_f(vv);
    }
}

// ---------------- kernel: recurrent scan ----------------
// One warp per (b,k,v) column of the state (1024 independent warps).
// Lane n holds S[n][v]. Per step: S = d*S + k[n]*v[v]; y[v] = sum_n q[n]*S.
__global__ void scan_kernel(const float* __restrict__ S0,
                            float* __restrict__ sfin) {
    int lane = threadIdx.x & 31;
    int gw = blockIdx.x * (blockDim.x >> 5) + (threadIdx.x >> 5);  // 0..1023
    int b = gw >> 8;
    int rem = gw & 255;
    int k = rem >> 5;
    int v = rem & 31;
    int n = lane;

    float S = S0[((size_t)(b * KK + k) * 32 + n) * 32 + v];
    size_t base = (size_t)b * TT * KK + k;   // slot index for t=0
    // prefetch t=0
    float kn = g_ksel[base * 32 + n];
    float qn = g_qsel[base * 32 + n];
    float vv = g_vsel[base * 32 + v];
    float dd = g_dsel[base];

    for (int t = 0; t < TT; t++) {
        float knc = kn, qnc = qn, vvc = vv, ddc = dd;
        size_t nbase = base + KK;
        if (t + 1 < TT) {
            kn = g_ksel[nbase * 32 + n];
            qn = g_qsel[nbase * 32 + n];
            vv = g_vsel[nbase * 32 + v];
            dd = g_dsel[nbase];
        }
        S = fmaf(ddc, S, knc * vvc);
        float p = qnc * S;
#pragma unroll
        for (int o = 16; o > 0; o >>= 1) p += __shfl_xor_sync(0xffffffffu, p, o);
        if (lane == 0) g_yslot[base * 32 + v] = p;
        base = nbase;
    }
    if (sfin)
        sfin[((size_t)(b * KK + k) * 32 + n) * 32 + v] = S;
}

// ---------------- kernel: slot reduce + output projection ----------------
// Block = 8 tokens; reuse WoT across tokens (L2-friendly).
__global__ void outproj_kernel(float* __restrict__ out) {
    __shared__ float ysum[8][33];
    int tid = threadIdx.x;
    int tok0 = blockIdx.x * 8;
    {
        int tk = tid >> 5, v = tid & 31;
        float s = 0.0f;
        size_t p = (size_t)(tok0 + tk) * KK * 32 + v;
#pragma unroll
        for (int kk = 0; kk < KK; kk++) s += g_yslot[p + kk * 32];
        ysum[tk][v] = s;
    }
    __syncthreads();
    float acc[8][4];
#pragma unroll
    for (int tk = 0; tk < 8; tk++)
#pragma unroll
        for (int j = 0; j < 4; j++) acc[tk][j] = 0.0f;

#pragma unroll 4
    for (int vv = 0; vv < 32; vv++) {
        float w0 = g_WoT[vv * DD + tid];
        float w1 = g_WoT[vv * DD + tid + 256];
        float w2 = g_WoT[vv * DD + tid + 512];
        float w3 = g_WoT[vv * DD + tid + 768];
#pragma unroll
        for (int tk = 0; tk < 8; tk++) {
            float y = ysum[tk][vv];
            acc[tk][0] = fmaf(w0, y, acc[tk][0]);
            acc[tk][1] = fmaf(w1, y, acc[tk][1]);
            acc[tk][2] = fmaf(w2, y, acc[tk][2]);
            acc[tk][3] = fmaf(w3, y, acc[tk][3]);
        }
    }
#pragma unroll
    for (int tk = 0; tk < 8; tk++)
#pragma unroll
        for (int j = 0; j < 4; j++)
            out[(size_t)(tok0 + tk) * DD + j * 256 + tid] = acc[tk][j];
}

// ---------------- launch ----------------
extern "C" void kernel_launch(void* const* d_in, const int* in_sizes, int n_in,
                              void* d_out, int out_size) {
    const float* x       = (const float*)d_in[0];
    const float* Wr      = (const float*)d_in[1];
    const float* Wq      = (const float*)d_in[2];
    const float* Wk      = (const float*)d_in[3];
    const float* Wv      = (const float*)d_in[4];
    const float* Wa      = (const float*)d_in[5];
    const float* A_log   = (const float*)d_in[6];
    const float* dt_bias = (const float*)d_in[7];
    const float* Wo      = (const float*)d_in[8];
    const float* S0      = (const float*)d_in[9];
    float* out = (float*)d_out;

    const long y_elems = (long)NT * DD;
    const long s_elems = (long)BB * KK * NSd * HVd;
    float* sfin = ((long)out_size >= y_elems + s_elems) ? (out + y_elems) : nullptr;

    zero_counts<<<1, 64>>>();
    transpose_wo<<<128, 256>>>(Wo);
    gemm_ra<<<NT / 64, 256>>>(x, Wr, Wa);
    route_kernel<<<NT / 8, 256>>>(A_log, dt_bias);
    prefix_kernel<<<1, 32>>>();
    scatter_kernel<<<NTS / 256, 256>>>();
    gemm_qkv<<<dim3(MAXTILES, HH), 256>>>(x, Wq, Wk, Wv);
    scan_kernel<<<128, 256>>>(S0, sfin);
    outproj_kernel<<<NT / 8, 256>>>(out);
}

// round 2
// speedup vs baseline: 1.0169x; 1.0169x over previous
#include <cuda_runtime.h>
#include <math.h>

// Problem constants
#define BB   4
#define TT   2048
#define DD   1024
#define HH   64
#define NSd  32
#define KK   8
#define HVd  32
#define NT   8192      // BB*TT tokens
#define NTS  65536     // NT*KK token-slots
#define MAXTILES 64    // up to 4096 tokens per head (expected ~1024)

// ---------------- scratch (static device memory; no allocation) ----------------
__device__ float g_ra[NT * 128];          // [token][0:64]=router logits, [64:128]=a
__device__ int   g_topi[NTS];             // selected head per (token,slot)
__device__ float g_rw[NTS];               // renormalized router weight
__device__ float g_dsel[NTS];             // decay per (token,slot)
__device__ int   g_count[HH];
__device__ int   g_offset[HH];
__device__ int   g_cursor[HH];
__device__ int   g_list[NTS];             // per-head token-slot lists
__device__ float g_qsel[NTS * 32];        // l2norm(silu(q)) * rw
__device__ float g_ksel[NTS * 32];        // l2norm(silu(k))
__device__ float g_vsel[NTS * 32];        // silu(v)
__device__ float g_yslot[NTS * 32];       // per-slot read output
__device__ float g_WoT[32 * DD];          // Wo transposed [v][d]

// ---------------- small helpers ----------------
__device__ __forceinline__ float silu_f(float x) {
    return x / (1.0f + expf(-x));
}

// tf32 split: x = hi + lo, both representable as tf32
__device__ __forceinline__ void tf32_split(float x, unsigned& hi, unsigned& lo) {
    unsigned h;
    asm("cvt.rna.tf32.f32 %0, %1;" : "=r"(h) : "f"(x));
    float hf = __uint_as_float(h);
    float l = x - hf;
    unsigned lb;
    asm("cvt.rna.tf32.f32 %0, %1;" : "=r"(lb) : "f"(l));
    hi = h; lo = lb;
}

// m16n8k8 tf32 mma, D = A*B + D
__device__ __forceinline__ void mma_tf32(float* c, const unsigned* a, const unsigned* b) {
    asm volatile(
        "mma.sync.aligned.m16n8k8.row.col.f32.tf32.tf32.f32 "
        "{%0,%1,%2,%3}, {%4,%5,%6,%7}, {%8,%9}, {%0,%1,%2,%3};"
        : "+f"(c[0]), "+f"(c[1]), "+f"(c[2]), "+f"(c[3])
        : "r"(a[0]), "r"(a[1]), "r"(a[2]), "r"(a[3]), "r"(b[0]), "r"(b[1]));
}

// ---------------- kernel: zero counters ----------------
__global__ void zero_counts() {
    int h = threadIdx.x;
    if (h < HH) { g_count[h] = 0; g_cursor[h] = 0; }
}

// ---------------- kernel: transpose Wo [DD][32] -> [32][DD] ----------------
__global__ void transpose_wo(const float* __restrict__ Wo) {
    int o = blockIdx.x * 256 + threadIdx.x;   // 0..32767
    int v = o >> 10, d = o & 1023;
    g_WoT[o] = Wo[d * 32 + v];
}

// ---------------- kernel: router + decay GEMM (tensor core, tf32 3-pass) ----------------
// g_ra[64 tokens][128] = x @ [Wr;Wa]^T.  BM=64, BN=128, BK=16.
// 8 warps: 4 row-warps x 2 col-warps; warp tile 16x64 = 8 n-atoms of m16n8k8.
__global__ void gemm_ra_tc(const float* __restrict__ x,
                           const float* __restrict__ Wr,
                           const float* __restrict__ Wa) {
    __shared__ __align__(16) float sA[2 * 16 * 72];    // hi, lo  [k][row] stride 72
    __shared__ __align__(16) float sW[2 * 16 * 136];   // hi, lo  [k][col] stride 136
    float* Ahi = sA;            float* Alo = sA + 16 * 72;
    float* Whi = sW;            float* Wlo = sW + 16 * 136;

    int tid = threadIdx.x;
    int m0 = blockIdx.x * 64;
    int w = tid >> 5, lane = tid & 31;
    int mw = w >> 1, nw = w & 1;
    int g = lane >> 2, tig = lane & 3;

    float acc[8][4];
#pragma unroll
    for (int i = 0; i < 8; i++)
#pragma unroll
        for (int j = 0; j < 4; j++) acc[i][j] = 0.0f;

    int xr = tid >> 2;            // 0..63
    int xc = (tid & 3) * 4;       // 0,4,8,12

    for (int k0 = 0; k0 < DD; k0 += 16) {
        // X tile 64x16
        {
            const float4 p = *(const float4*)(x + (size_t)(m0 + xr) * DD + k0 + xc);
            float xv[4] = {p.x, p.y, p.z, p.w};
#pragma unroll
            for (int j = 0; j < 4; j++) {
                unsigned h_, l_; tf32_split(xv[j], h_, l_);
                Ahi[(xc + j) * 72 + xr] = __uint_as_float(h_);
                Alo[(xc + j) * 72 + xr] = __uint_as_float(l_);
            }
        }
        // W tile 128x16 (rows 0-63 Wr, 64-127 Wa)
#pragma unroll
        for (int it = 0; it < 2; it++) {
            int u = tid + it * 256;
            int r = u >> 2, c = (u & 3) * 4;
            const float* src = (r < 64) ? (Wr + (size_t)r * DD)
                                        : (Wa + (size_t)(r - 64) * DD);
            const float4 p = *(const float4*)(src + k0 + c);
            float wv[4] = {p.x, p.y, p.z, p.w};
#pragma unroll
            for (int j = 0; j < 4; j++) {
                unsigned h_, l_; tf32_split(wv[j], h_, l_);
                Whi[(c + j) * 136 + r] = __uint_as_float(h_);
                Wlo[(c + j) * 136 + r] = __uint_as_float(l_);
            }
        }
        __syncthreads();
#pragma unroll
        for (int ka = 0; ka < 2; ka++) {
            int kb = ka * 8;
            int row0 = mw * 16 + g;
            unsigned ahi[4], alo[4];
            ahi[0] = __float_as_uint(Ahi[(kb + tig) * 72 + row0]);
            ahi[1] = __float_as_uint(Ahi[(kb + tig) * 72 + row0 + 8]);
            ahi[2] = __float_as_uint(Ahi[(kb + tig + 4) * 72 + row0]);
            ahi[3] = __float_as_uint(Ahi[(kb + tig + 4) * 72 + row0 + 8]);
            alo[0] = __float_as_uint(Alo[(kb + tig) * 72 + row0]);
            alo[1] = __float_as_uint(Alo[(kb + tig) * 72 + row0 + 8]);
            alo[2] = __float_as_uint(Alo[(kb + tig + 4) * 72 + row0]);
            alo[3] = __float_as_uint(Alo[(kb + tig + 4) * 72 + row0 + 8]);
#pragma unroll
            for (int na = 0; na < 8; na++) {
                int col = nw * 64 + na * 8 + g;
                unsigned bhi[2], blo[2];
                bhi[0] = __float_as_uint(Whi[(kb + tig) * 136 + col]);
                bhi[1] = __float_as_uint(Whi[(kb + tig + 4) * 136 + col]);
                blo[0] = __float_as_uint(Wlo[(kb + tig) * 136 + col]);
                blo[1] = __float_as_uint(Wlo[(kb + tig + 4) * 136 + col]);
                mma_tf32(acc[na], ahi, bhi);
                mma_tf32(acc[na], ahi, blo);
                mma_tf32(acc[na], alo, bhi);
            }
        }
        __syncthreads();
    }
    // direct store (C fragment: c0 at (row,col=tig*2), c1 +1, c2 row+8)
#pragma unroll
    for (int na = 0; na < 8; na++) {
        int col = nw * 64 + na * 8 + tig * 2;
        int row = m0 + mw * 16 + g;
        *(float2*)&g_ra[(size_t)row * 128 + col]       = make_float2(acc[na][0], acc[na][1]);
        *(float2*)&g_ra[(size_t)(row + 8) * 128 + col] = make_float2(acc[na][2], acc[na][3]);
    }
}

// ---------------- kernel: routing (top-8, rw, decay) ----------------
__global__ void route_kernel(const float* __restrict__ A_log,
                             const float* __restrict__ dt_bias) {
    int lane = threadIdx.x & 31;
    int w = threadIdx.x >> 5;
    int tok = blockIdx.x * 8 + w;
    const float* ra = g_ra + (size_t)tok * 128;
    float v0 = ra[lane], v1 = ra[lane + 32];
    int i0 = lane, i1 = lane + 32;
    float topv[8]; int tophi[8];
#pragma unroll
    for (int it = 0; it < 8; it++) {
        float bv; int bi;
        if (v0 > v1 || (v0 == v1 && i0 < i1)) { bv = v0; bi = i0; }
        else                                  { bv = v1; bi = i1; }
#pragma unroll
        for (int off = 16; off > 0; off >>= 1) {
            float ov = __shfl_xor_sync(0xffffffffu, bv, off);
            int   oi = __shfl_xor_sync(0xffffffffu, bi, off);
            if (ov > bv || (ov == bv && oi < bi)) { bv = ov; bi = oi; }
        }
        topv[it] = bv; tophi[it] = bi;
        if (bi == i0) v0 = -INFINITY;
        if (bi == i1) v1 = -INFINITY;
    }
    float s = 0.0f;
#pragma unroll
    for (int j = 0; j < 8; j++) s += expf(topv[j] - topv[0]);

    float myv = 0.0f; int myh = 0;
#pragma unroll
    for (int it = 0; it < 8; it++)
        if (lane == it) { myv = topv[it]; myh = tophi[it]; }

    if (lane < 8) {
        float rw = expf(myv - topv[0]) / s;
        float z = ra[64 + myh] + dt_bias[myh];
        float sp = (z > 20.0f) ? z : log1pf(expf(z));
        float dec = expf(-expf(A_log[myh]) * sp);
        int e = tok * 8 + lane;
        g_topi[e] = myh;
        g_rw[e] = rw;
        g_dsel[e] = dec;
        atomicAdd(&g_count[myh], 1);
    }
}

// ---------------- kernel: prefix sum over 64 head counts ----------------
__global__ void prefix_kernel() {
    if (threadIdx.x == 0) {
        int acc = 0;
        for (int h = 0; h < HH; h++) { g_offset[h] = acc; acc += g_count[h]; }
    }
}

// ---------------- kernel: scatter token-slots into per-head lists ----------------
__global__ void scatter_kernel() {
    int e = blockIdx.x * 256 + threadIdx.x;
    int h = g_topi[e];
    int pos = atomicAdd(&g_cursor[h], 1);
    g_list[g_offset[h] + pos] = e;
}

// ---------------- kernel: grouped q/k/v GEMM (tensor core, tf32 3-pass) ----------------
// For head h: C[64 tokens][96] = Xg[64][1024] * [Wq_h; Wk_h; Wv_h]^T
// BM=64, BN=96, BK=32. 8 warps: 4 row x 2 col; warp tile 16x48 = 6 n-atoms.
// Epilogue: silu + l2norm(q,k), silu(v), q scaled by rw. Compact output.
__global__ void gemm_qkv_tc(const float* __restrict__ x,
                            const float* __restrict__ Wq,
                            const float* __restrict__ Wk,
                            const float* __restrict__ Wv) {
    __shared__ int s_ent[64];
    __shared__ __align__(16) float sbuf[11264];   // A(hi,lo)[32][72] + W(hi,lo)[32][104]; Cs overlay
    float* Ahi = sbuf;                 // 2304
    float* Alo = sbuf + 2304;          // 2304
    float* Whi = sbuf + 4608;          // 3328
    float* Wlo = sbuf + 7936;          // 3328
    float* Cs  = sbuf;                 // overlay after mainloop: [64][97]

    int tid = threadIdx.x;
    int h = blockIdx.y;
    int cnt = g_count[h];
    int t0 = blockIdx.x * 64;
    if (t0 >= cnt) return;
    int off = g_offset[h];
    if (tid < 64) s_ent[tid] = (t0 + tid < cnt) ? g_list[off + t0 + tid] : -1;
    __syncthreads();

    int w = tid >> 5, lane = tid & 31;
    int mw = w >> 1, nw = w & 1;
    int g = lane >> 2, tig = lane & 3;

    float acc[6][4];
#pragma unroll
    for (int i = 0; i < 6; i++)
#pragma unroll
        for (int j = 0; j < 4; j++) acc[i][j] = 0.0f;

    int xr = tid >> 2;            // 0..63
    int xc = (tid & 3) * 8;       // 0,8,16,24
    int e_my = s_ent[xr];
    const float* xrow = (e_my >= 0) ? (x + (size_t)(e_my >> 3) * DD + xc) : nullptr;

    for (int k0 = 0; k0 < DD; k0 += 32) {
        // gathered X tile 64x32 (8 floats per thread)
        {
            float xv[8] = {0.f,0.f,0.f,0.f,0.f,0.f,0.f,0.f};
            if (e_my >= 0) {
                const float4 p0 = *(const float4*)(xrow + k0);
                const float4 p1 = *(const float4*)(xrow + k0 + 4);
                xv[0]=p0.x; xv[1]=p0.y; xv[2]=p0.z; xv[3]=p0.w;
                xv[4]=p1.x; xv[5]=p1.y; xv[6]=p1.z; xv[7]=p1.w;
            }
#pragma unroll
            for (int j = 0; j < 8; j++) {
                unsigned h_, l_; tf32_split(xv[j], h_, l_);
                Ahi[(xc + j) * 72 + xr] = __uint_as_float(h_);
                Alo[(xc + j) * 72 + xr] = __uint_as_float(l_);
            }
        }
        // W tile 96x32 (rows 0-31 Wq, 32-63 Wk, 64-95 Wv) : 384 units of 8 floats
#pragma unroll
        for (int it = 0; it < 2; it++) {
            int u = tid + it * 256;
            if (u < 384) {
                int r = u >> 2, c = (u & 3) * 8;
                const float* src = (r < 32) ? (Wq + (size_t)(h * 32 + r) * DD)
                                 : (r < 64) ? (Wk + (size_t)(h * 32 + r - 32) * DD)
                                            : (Wv + (size_t)(h * 32 + r - 64) * DD);
                const float4 p0 = *(const float4*)(src + k0 + c);
                const float4 p1 = *(const float4*)(src + k0 + c + 4);
                float wv[8] = {p0.x, p0.y, p0.z, p0.w, p1.x, p1.y, p1.z, p1.w};
#pragma unroll
                for (int j = 0; j < 8; j++) {
                    unsigned h_, l_; tf32_split(wv[j], h_, l_);
                    Whi[(c + j) * 104 + r] = __uint_as_float(h_);
                    Wlo[(c + j) * 104 + r] = __uint_as_float(l_);
                }
            }
        }
        __syncthreads();
#pragma unroll
        for (int ka = 0; ka < 4; ka++) {
            int kb = ka * 8;
            int row0 = mw * 16 + g;
            unsigned ahi[4], alo[4];
            ahi[0] = __float_as_uint(Ahi[(kb + tig) * 72 + row0]);
            ahi[1] = __float_as_uint(Ahi[(kb + tig) * 72 + row0 + 8]);
            ahi[2] = __float_as_uint(Ahi[(kb + tig + 4) * 72 + row0]);
            ahi[3] = __float_as_uint(Ahi[(kb + tig + 4) * 72 + row0 + 8]);
            alo[0] = __float_as_uint(Alo[(kb + tig) * 72 + row0]);
            alo[1] = __float_as_uint(Alo[(kb + tig) * 72 + row0 + 8]);
            alo[2] = __float_as_uint(Alo[(kb + tig + 4) * 72 + row0]);
            alo[3] = __float_as_uint(Alo[(kb + tig + 4) * 72 + row0 + 8]);
#pragma unroll
            for (int na = 0; na < 6; na++) {
                int col = nw * 48 + na * 8 + g;
                unsigned bhi[2], blo[2];
                bhi[0] = __float_as_uint(Whi[(kb + tig) * 104 + col]);
                bhi[1] = __float_as_uint(Whi[(kb + tig + 4) * 104 + col]);
                blo[0] = __float_as_uint(Wlo[(kb + tig) * 104 + col]);
                blo[1] = __float_as_uint(Wlo[(kb + tig + 4) * 104 + col]);
                mma_tf32(acc[na], ahi, bhi);
                mma_tf32(acc[na], ahi, blo);
                mma_tf32(acc[na], alo, bhi);
            }
        }
        __syncthreads();
    }

    // stage accumulators into Cs overlay
#pragma unroll
    for (int na = 0; na < 6; na++) {
        int col = nw * 48 + na * 8 + tig * 2;
        int row = mw * 16 + g;
        Cs[row * 97 + col]           = acc[na][0];
        Cs[row * 97 + col + 1]       = acc[na][1];
        Cs[(row + 8) * 97 + col]     = acc[na][2];
        Cs[(row + 8) * 97 + col + 1] = acc[na][3];
    }
    __syncthreads();

#pragma unroll 1
    for (int rep = 0; rep < 8; rep++) {
        int r = rep * 8 + w;
        int e = s_ent[r];
        if (e < 0) continue;
        float wr = g_rw[e];
        // q: silu -> l2norm -> * rw
        float qv = Cs[r * 97 + lane];
        float qs = silu_f(qv);
        float ssq = qs * qs;
#pragma unroll
        for (int o = 16; o > 0; o >>= 1) ssq += __shfl_xor_sync(0xffffffffu, ssq, o);
        g_qsel[(size_t)e * 32 + lane] = qs * rsqrtf(ssq + 1e-6f) * wr;
        // k: silu -> l2norm
        float kv = Cs[r * 97 + 32 + lane];
        float ks = silu_f(kv);
        float ssk = ks * ks;
#pragma unroll
        for (int o = 16; o > 0; o >>= 1) ssk += __shfl_xor_sync(0xffffffffu, ssk, o);
        g_ksel[(size_t)e * 32 + lane] = ks * rsqrtf(ssk + 1e-6f);
        // v: silu
        float vv = Cs[r * 97 + 64 + lane];
        g_vsel[(size_t)e * 32 + lane] = silu_f(vv);
    }
}

// ---------------- kernel: recurrent scan ----------------
// One warp per (b,k,v) column of the state (1024 independent warps).
// Lane n holds S[n][v]. Per step: S = d*S + k[n]*v[v]; y[v] = sum_n q[n]*S.
__global__ void scan_kernel(const float* __restrict__ S0,
                            float* __restrict__ sfin) {
    int lane = threadIdx.x & 31;
    int gw = blockIdx.x * (blockDim.x >> 5) + (threadIdx.x >> 5);  // 0..1023
    int b = gw >> 8;
    int rem = gw & 255;
    int k = rem >> 5;
    int v = rem & 31;
    int n = lane;

    float S = S0[((size_t)(b * KK + k) * 32 + n) * 32 + v];
    size_t base = (size_t)b * TT * KK + k;   // slot index for t=0
    float kn = g_ksel[base * 32 + n];
    float qn = g_qsel[base * 32 + n];
    float vv = g_vsel[base * 32 + v];
    float dd = g_dsel[base];

    for (int t = 0; t < TT; t++) {
        float knc = kn, qnc = qn, vvc = vv, ddc = dd;
        size_t nbase = base + KK;
        if (t + 1 < TT) {
            kn = g_ksel[nbase * 32 + n];
            qn = g_qsel[nbase * 32 + n];
            vv = g_vsel[nbase * 32 + v];
            dd = g_dsel[nbase];
        }
        S = fmaf(ddc, S, knc * vvc);
        float p = qnc * S;
#pragma unroll
        for (int o = 16; o > 0; o >>= 1) p += __shfl_xor_sync(0xffffffffu, p, o);
        if (lane == 0) g_yslot[base * 32 + v] = p;
        base = nbase;
    }
    if (sfin)
        sfin[((size_t)(b * KK + k) * 32 + n) * 32 + v] = S;
}

// ---------------- kernel: slot reduce + output projection ----------------
__global__ void outproj_kernel(float* __restrict__ out) {
    __shared__ float ysum[8][33];
    int tid = threadIdx.x;
    int tok0 = blockIdx.x * 8;
    {
        int tk = tid >> 5, v = tid & 31;
        float s = 0.0f;
        size_t p = (size_t)(tok0 + tk) * KK * 32 + v;
#pragma unroll
        for (int kk = 0; kk < KK; kk++) s += g_yslot[p + kk * 32];
        ysum[tk][v] = s;
    }
    __syncthreads();
    float acc[8][4];
#pragma unroll
    for (int tk = 0; tk < 8; tk++)
#pragma unroll
        for (int j = 0; j < 4; j++) acc[tk][j] = 0.0f;

#pragma unroll 4
    for (int vv = 0; vv < 32; vv++) {
        float w0 = g_WoT[vv * DD + tid];
        float w1 = g_WoT[vv * DD + tid + 256];
        float w2 = g_WoT[vv * DD + tid + 512];
        float w3 = g_WoT[vv * DD + tid + 768];
#pragma unroll
        for (int tk = 0; tk < 8; tk++) {
            float y = ysum[tk][vv];
            acc[tk][0] = fmaf(w0, y, acc[tk][0]);
            acc[tk][1] = fmaf(w1, y, acc[tk][1]);
            acc[tk][2] = fmaf(w2, y, acc[tk][2]);
            acc[tk][3] = fmaf(w3, y, acc[tk][3]);
        }
    }
#pragma unroll
    for (int tk = 0; tk < 8; tk++)
#pragma unroll
        for (int j = 0; j < 4; j++)
            out[(size_t)(tok0 + tk) * DD + j * 256 + tid] = acc[tk][j];
}

// ---------------- launch ----------------
extern "C" void kernel_launch(void* const* d_in, const int* in_sizes, int n_in,
                              void* d_out, int out_size) {
    const float* x       = (const float*)d_in[0];
    const float* Wr      = (const float*)d_in[1];
    const float* Wq      = (const float*)d_in[2];
    const float* Wk      = (const float*)d_in[3];
    const float* Wv      = (const float*)d_in[4];
    const float* Wa      = (const float*)d_in[5];
    const float* A_log   = (const float*)d_in[6];
    const float* dt_bias = (const float*)d_in[7];
    const float* Wo      = (const float*)d_in[8];
    const float* S0      = (const float*)d_in[9];
    float* out = (float*)d_out;

    const long y_elems = (long)NT * DD;
    const long s_elems = (long)BB * KK * NSd * HVd;
    float* sfin = ((long)out_size >= y_elems + s_elems) ? (out + y_elems) : nullptr;

    zero_counts<<<1, 64>>>();
    transpose_wo<<<128, 256>>>(Wo);
    gemm_ra_tc<<<NT / 64, 256>>>(x, Wr, Wa);
    route_kernel<<<NT / 8, 256>>>(A_log, dt_bias);
    prefix_kernel<<<1, 32>>>();
    scatter_kernel<<<NTS / 256, 256>>>();
    gemm_qkv_tc<<<dim3(MAXTILES, HH), 256>>>(x, Wq, Wk, Wv);
    scan_kernel<<<128, 256>>>(S0, sfin);
    outproj_kernel<<<NT / 8, 256>>>(out);
}

// round 4
// speedup vs baseline: 1.8587x; 1.8277x over previous
#include <cuda_runtime.h>
#include <math.h>

// Problem constants
#define BB   4
#define TT   2048
#define DD   1024
#define HH   64
#define NSd  32
#define KK   8
#define HVd  32
#define NT   8192      // BB*TT tokens
#define NTS  65536     // NT*KK token-slots
#define MAXTILES 64
#define CC   64        // chunk length
#define NCH  32        // chunks per sequence (TT/CC)
#define NCHUNKS 1024   // BB*KK*NCH

// ---------------- scratch (static device memory; no allocation) ----------------
__device__ float g_ra[NT * 128];
__device__ int   g_topi[NTS];
__device__ float g_rw[NTS];
__device__ float g_dsel[NTS];             // per-slot decay EXPONENT (<=0)
__device__ int   g_count[HH];
__device__ int   g_offset[HH];
__device__ int   g_cursor[HH];
__device__ int   g_list[NTS];
__device__ float g_qsel[NTS * 32];        // phase1 overwrites with qd = q*exp(L)
__device__ float g_ksel[NTS * 32];
__device__ float g_vsel[NTS * 32];
__device__ float g_yslot[NTS * 32];
__device__ float g_WoT[32 * DD];
__device__ float g_U[NCHUNKS * 1024];     // per-chunk state increment [n][v]
__device__ float g_P63[NCHUNKS];          // per-chunk total decay
__device__ float g_Schunk[NCHUNKS * 1024];// state at chunk START

// ---------------- helpers ----------------
__device__ __forceinline__ float silu_f(float x) {
    return x / (1.0f + expf(-x));
}

__device__ __forceinline__ void tf32_split(float x, unsigned& hi, unsigned& lo) {
    unsigned h;
    asm("cvt.rna.tf32.f32 %0, %1;" : "=r"(h) : "f"(x));
    float hf = __uint_as_float(h);
    float l = x - hf;
    unsigned lb;
    asm("cvt.rna.tf32.f32 %0, %1;" : "=r"(lb) : "f"(l));
    hi = h; lo = lb;
}

__device__ __forceinline__ void mma_tf32(float* c, const unsigned* a, const unsigned* b) {
    asm volatile(
        "mma.sync.aligned.m16n8k8.row.col.f32.tf32.tf32.f32 "
        "{%0,%1,%2,%3}, {%4,%5,%6,%7}, {%8,%9}, {%0,%1,%2,%3};"
        : "+f"(c[0]), "+f"(c[1]), "+f"(c[2]), "+f"(c[3])
        : "r"(a[0]), "r"(a[1]), "r"(a[2]), "r"(a[3]), "r"(b[0]), "r"(b[1]));
}

// ---------------- kernel: zero counters ----------------
__global__ void zero_counts() {
    int h = threadIdx.x;
    if (h < HH) { g_count[h] = 0; g_cursor[h] = 0; }
}

// ---------------- kernel: transpose Wo ----------------
__global__ void transpose_wo(const float* __restrict__ Wo) {
    int o = blockIdx.x * 256 + threadIdx.x;
    int v = o >> 10, d = o & 1023;
    g_WoT[o] = Wo[d * 32 + v];
}

// ---------------- kernel: router + decay GEMM (tf32 3-pass) ----------------
__global__ void gemm_ra_tc(const float* __restrict__ x,
                           const float* __restrict__ Wr,
                           const float* __restrict__ Wa) {
    __shared__ __align__(16) float sA[2 * 16 * 72];
    __shared__ __align__(16) float sW[2 * 16 * 136];
    float* Ahi = sA;            float* Alo = sA + 16 * 72;
    float* Whi = sW;            float* Wlo = sW + 16 * 136;

    int tid = threadIdx.x;
    int m0 = blockIdx.x * 64;
    int w = tid >> 5, lane = tid & 31;
    int mw = w >> 1, nw = w & 1;
    int g = lane >> 2, tig = lane & 3;

    float acc[8][4];
#pragma unroll
    for (int i = 0; i < 8; i++)
#pragma unroll
        for (int j = 0; j < 4; j++) acc[i][j] = 0.0f;

    int xr = tid >> 2;
    int xc = (tid & 3) * 4;

    for (int k0 = 0; k0 < DD; k0 += 16) {
        {
            const float4 p = *(const float4*)(x + (size_t)(m0 + xr) * DD + k0 + xc);
            float xv[4] = {p.x, p.y, p.z, p.w};
#pragma unroll
            for (int j = 0; j < 4; j++) {
                unsigned h_, l_; tf32_split(xv[j], h_, l_);
                Ahi[(xc + j) * 72 + xr] = __uint_as_float(h_);
                Alo[(xc + j) * 72 + xr] = __uint_as_float(l_);
            }
        }
#pragma unroll
        for (int it = 0; it < 2; it++) {
            int u = tid + it * 256;
            int r = u >> 2, c = (u & 3) * 4;
            const float* src = (r < 64) ? (Wr + (size_t)r * DD)
                                        : (Wa + (size_t)(r - 64) * DD);
            const float4 p = *(const float4*)(src + k0 + c);
            float wv[4] = {p.x, p.y, p.z, p.w};
#pragma unroll
            for (int j = 0; j < 4; j++) {
                unsigned h_, l_; tf32_split(wv[j], h_, l_);
                Whi[(c + j) * 136 + r] = __uint_as_float(h_);
                Wlo[(c + j) * 136 + r] = __uint_as_float(l_);
            }
        }
        __syncthreads();
#pragma unroll
        for (int ka = 0; ka < 2; ka++) {
            int kb = ka * 8;
            int row0 = mw * 16 + g;
            unsigned ahi[4], alo[4];
            ahi[0] = __float_as_uint(Ahi[(kb + tig) * 72 + row0]);
            ahi[1] = __float_as_uint(Ahi[(kb + tig) * 72 + row0 + 8]);
            ahi[2] = __float_as_uint(Ahi[(kb + tig + 4) * 72 + row0]);
            ahi[3] = __float_as_uint(Ahi[(kb + tig + 4) * 72 + row0 + 8]);
            alo[0] = __float_as_uint(Alo[(kb + tig) * 72 + row0]);
            alo[1] = __float_as_uint(Alo[(kb + tig) * 72 + row0 + 8]);
            alo[2] = __float_as_uint(Alo[(kb + tig + 4) * 72 + row0]);
            alo[3] = __float_as_uint(Alo[(kb + tig + 4) * 72 + row0 + 8]);
#pragma unroll
            for (int na = 0; na < 8; na++) {
                int col = nw * 64 + na * 8 + g;
                unsigned bhi[2], blo[2];
                bhi[0] = __float_as_uint(Whi[(kb + tig) * 136 + col]);
                bhi[1] = __float_as_uint(Whi[(kb + tig + 4) * 136 + col]);
                blo[0] = __float_as_uint(Wlo[(kb + tig) * 136 + col]);
                blo[1] = __float_as_uint(Wlo[(kb + tig + 4) * 136 + col]);
                mma_tf32(acc[na], ahi, bhi);
                mma_tf32(acc[na], ahi, blo);
                mma_tf32(acc[na], alo, bhi);
            }
        }
        __syncthreads();
    }
#pragma unroll
    for (int na = 0; na < 8; na++) {
        int col = nw * 64 + na * 8 + tig * 2;
        int row = m0 + mw * 16 + g;
        *(float2*)&g_ra[(size_t)row * 128 + col]       = make_float2(acc[na][0], acc[na][1]);
        *(float2*)&g_ra[(size_t)(row + 8) * 128 + col] = make_float2(acc[na][2], acc[na][3]);
    }
}

// ---------------- kernel: routing (top-8, rw, decay exponent) ----------------
__global__ void route_kernel(const float* __restrict__ A_log,
                             const float* __restrict__ dt_bias) {
    int lane = threadIdx.x & 31;
    int w = threadIdx.x >> 5;
    int tok = blockIdx.x * 8 + w;
    const float* ra = g_ra + (size_t)tok * 128;
    float v0 = ra[lane], v1 = ra[lane + 32];
    int i0 = lane, i1 = lane + 32;
    float topv[8]; int tophi[8];
#pragma unroll
    for (int it = 0; it < 8; it++) {
        float bv; int bi;
        if (v0 > v1 || (v0 == v1 && i0 < i1)) { bv = v0; bi = i0; }
        else                                  { bv = v1; bi = i1; }
#pragma unroll
        for (int off = 16; off > 0; off >>= 1) {
            float ov = __shfl_xor_sync(0xffffffffu, bv, off);
            int   oi = __shfl_xor_sync(0xffffffffu, bi, off);
            if (ov > bv || (ov == bv && oi < bi)) { bv = ov; bi = oi; }
        }
        topv[it] = bv; tophi[it] = bi;
        if (bi == i0) v0 = -INFINITY;
        if (bi == i1) v1 = -INFINITY;
    }
    float s = 0.0f;
#pragma unroll
    for (int j = 0; j < 8; j++) s += expf(topv[j] - topv[0]);

    float myv = 0.0f; int myh = 0;
#pragma unroll
    for (int it = 0; it < 8; it++)
        if (lane == it) { myv = topv[it]; myh = tophi[it]; }

    if (lane < 8) {
        float rw = expf(myv - topv[0]) / s;
        float z = ra[64 + myh] + dt_bias[myh];
        float sp = (z > 20.0f) ? z : log1pf(expf(z));
        int e = tok * 8 + lane;
        g_topi[e] = myh;
        g_rw[e] = rw;
        g_dsel[e] = -expf(A_log[myh]) * sp;   // decay EXPONENT (log of decay)
        atomicAdd(&g_count[myh], 1);
    }
}

// ---------------- kernel: prefix sum ----------------
__global__ void prefix_kernel() {
    if (threadIdx.x == 0) {
        int acc = 0;
        for (int h = 0; h < HH; h++) { g_offset[h] = acc; acc += g_count[h]; }
    }
}

// ---------------- kernel: scatter ----------------
__global__ void scatter_kernel() {
    int e = blockIdx.x * 256 + threadIdx.x;
    int h = g_topi[e];
    int pos = atomicAdd(&g_cursor[h], 1);
    g_list[g_offset[h] + pos] = e;
}

// ---------------- kernel: grouped q/k/v GEMM (tf32 3-pass) ----------------
__global__ void gemm_qkv_tc(const float* __restrict__ x,
                            const float* __restrict__ Wq,
                            const float* __restrict__ Wk,
                            const float* __restrict__ Wv) {
    __shared__ int s_ent[64];
    __shared__ __align__(16) float sbuf[11264];
    float* Ahi = sbuf;
    float* Alo = sbuf + 2304;
    float* Whi = sbuf + 4608;
    float* Wlo = sbuf + 7936;
    float* Cs  = sbuf;

    int tid = threadIdx.x;
    int h = blockIdx.y;
    int cnt = g_count[h];
    int t0 = blockIdx.x * 64;
    if (t0 >= cnt) return;
    int off = g_offset[h];
    if (tid < 64) s_ent[tid] = (t0 + tid < cnt) ? g_list[off + t0 + tid] : -1;
    __syncthreads();

    int w = tid >> 5, lane = tid & 31;
    int mw = w >> 1, nw = w & 1;
    int g = lane >> 2, tig = lane & 3;

    float acc[6][4];
#pragma unroll
    for (int i = 0; i < 6; i++)
#pragma unroll
        for (int j = 0; j < 4; j++) acc[i][j] = 0.0f;

    int xr = tid >> 2;
    int xc = (tid & 3) * 8;
    int e_my = s_ent[xr];
    const float* xrow = (e_my >= 0) ? (x + (size_t)(e_my >> 3) * DD + xc) : nullptr;

    for (int k0 = 0; k0 < DD; k0 += 32) {
        {
            float xv[8] = {0.f,0.f,0.f,0.f,0.f,0.f,0.f,0.f};
            if (e_my >= 0) {
                const float4 p0 = *(const float4*)(xrow + k0);
                const float4 p1 = *(const float4*)(xrow + k0 + 4);
                xv[0]=p0.x; xv[1]=p0.y; xv[2]=p0.z; xv[3]=p0.w;
                xv[4]=p1.x; xv[5]=p1.y; xv[6]=p1.z; xv[7]=p1.w;
            }
#pragma unroll
            for (int j = 0; j < 8; j++) {
                unsigned h_, l_; tf32_split(xv[j], h_, l_);
                Ahi[(xc + j) * 72 + xr] = __uint_as_float(h_);
                Alo[(xc + j) * 72 + xr] = __uint_as_float(l_);
            }
        }
#pragma unroll
        for (int it = 0; it < 2; it++) {
            int u = tid + it * 256;
            if (u < 384) {
                int r = u >> 2, c = (u & 3) * 8;
                const float* src = (r < 32) ? (Wq + (size_t)(h * 32 + r) * DD)
                                 : (r < 64) ? (Wk + (size_t)(h * 32 + r - 32) * DD)
                                            : (Wv + (size_t)(h * 32 + r - 64) * DD);
                const float4 p0 = *(const float4*)(src + k0 + c);
                const float4 p1 = *(const float4*)(src + k0 + c + 4);
                float wv[8] = {p0.x, p0.y, p0.z, p0.w, p1.x, p1.y, p1.z, p1.w};
#pragma unroll
                for (int j = 0; j < 8; j++) {
                    unsigned h_, l_; tf32_split(wv[j], h_, l_);
                    Whi[(c + j) * 104 + r] = __uint_as_float(h_);
                    Wlo[(c + j) * 104 + r] = __uint_as_float(l_);
                }
            }
        }
        __syncthreads();
#pragma unroll
        for (int ka = 0; ka < 4; ka++) {
            int kb = ka * 8;
            int row0 = mw * 16 + g;
            unsigned ahi[4], alo[4];
            ahi[0] = __float_as_uint(Ahi[(kb + tig) * 72 + row0]);
            ahi[1] = __float_as_uint(Ahi[(kb + tig) * 72 + row0 + 8]);
            ahi[2] = __float_as_uint(Ahi[(kb + tig + 4) * 72 + row0]);
            ahi[3] = __float_as_uint(Ahi[(kb + tig + 4) * 72 + row0 + 8]);
            alo[0] = __float_as_uint(Alo[(kb + tig) * 72 + row0]);
            alo[1] = __float_as_uint(Alo[(kb + tig) * 72 + row0 + 8]);
            alo[2] = __float_as_uint(Alo[(kb + tig + 4) * 72 + row0]);
            alo[3] = __float_as_uint(Alo[(kb + tig + 4) * 72 + row0 + 8]);
#pragma unroll
            for (int na = 0; na < 6; na++) {
                int col = nw * 48 + na * 8 + g;
                unsigned bhi[2], blo[2];
                bhi[0] = __float_as_uint(Whi[(kb + tig) * 104 + col]);
                bhi[1] = __float_as_uint(Whi[(kb + tig + 4) * 104 + col]);
                blo[0] = __float_as_uint(Wlo[(kb + tig) * 104 + col]);
                blo[1] = __float_as_uint(Wlo[(kb + tig + 4) * 104 + col]);
                mma_tf32(acc[na], ahi, bhi);
                mma_tf32(acc[na], ahi, blo);
                mma_tf32(acc[na], alo, bhi);
            }
        }
        __syncthreads();
    }

#pragma unroll
    for (int na = 0; na < 6; na++) {
        int col = nw * 48 + na * 8 + tig * 2;
        int row = mw * 16 + g;
        Cs[row * 97 + col]           = acc[na][0];
        Cs[row * 97 + col + 1]       = acc[na][1];
        Cs[(row + 8) * 97 + col]     = acc[na][2];
        Cs[(row + 8) * 97 + col + 1] = acc[na][3];
    }
    __syncthreads();

#pragma unroll 1
    for (int rep = 0; rep < 8; rep++) {
        int r = rep * 8 + w;
        int e = s_ent[r];
        if (e < 0) continue;
        float wr = g_rw[e];
        float qv = Cs[r * 97 + lane];
        float qs = silu_f(qv);
        float ssq = qs * qs;
#pragma unroll
        for (int o = 16; o > 0; o >>= 1) ssq += __shfl_xor_sync(0xffffffffu, ssq, o);
        g_qsel[(size_t)e * 32 + lane] = qs * rsqrtf(ssq + 1e-6f) * wr;
        float kv = Cs[r * 97 + 32 + lane];
        float ks = silu_f(kv);
        float ssk = ks * ks;
#pragma unroll
        for (int o = 16; o > 0; o >>= 1) ssk += __shfl_xor_sync(0xffffffffu, ssk, o);
        g_ksel[(size_t)e * 32 + lane] = ks * rsqrtf(ssk + 1e-6f);
        float vv = Cs[r * 97 + 64 + lane];
        g_vsel[(size_t)e * 32 + lane] = silu_f(vv);
    }
}

// ---------------- kernel: chunked scan phase 1 (intra-chunk) ----------------
// Block per chunk instance (b,kk,c). Computes:
//   L_i  = cumsum of decay exponents within chunk
//   A[i][s] = (q_i.k_s) * exp(L_i - L_s), s<=i
//   y_intra[i] = A @ v                  -> g_yslot
//   qd[i] = q_i * exp(L_i)              -> overwrites g_qsel
//   U[n][v] = sum_s k_s[n]*exp(L63-L_s)*v_s[v] -> g_U ;  g_P63 = exp(L63)
__global__ void chunk_intra() {
    __shared__ float qs[64][33], ks[64][33], vs[64][33];
    __shared__ float As[64][65];
    __shared__ float Ls[64], rr[64];
    int tid = threadIdx.x;
    int cid = blockIdx.x;
    int b = cid >> 8, kk = (cid >> 5) & 7, c = cid & 31;
    size_t e0 = ((size_t)(b * TT + c * CC)) * KK + kk;

#pragma unroll
    for (int it = 0; it < 2; it++) {
        int i = (tid >> 3) + it * 32;
        int c4 = (tid & 7) * 4;
        size_t gidx = (e0 + (size_t)i * KK) * 32 + c4;
        float4 qv = *(const float4*)&g_qsel[gidx];
        float4 kv = *(const float4*)&g_ksel[gidx];
        float4 vv = *(const float4*)&g_vsel[gidx];
        qs[i][c4] = qv.x; qs[i][c4+1] = qv.y; qs[i][c4+2] = qv.z; qs[i][c4+3] = qv.w;
        ks[i][c4] = kv.x; ks[i][c4+1] = kv.y; ks[i][c4+2] = kv.z; ks[i][c4+3] = kv.w;
        vs[i][c4] = vv.x; vs[i][c4+1] = vv.y; vs[i][c4+2] = vv.z; vs[i][c4+3] = vv.w;
    }
    if (tid < 64) Ls[tid] = g_dsel[e0 + (size_t)tid * KK];
    __syncthreads();
    if (tid == 0) {
        float a = 0.0f;
        for (int i = 0; i < 64; i++) { a += Ls[i]; Ls[i] = a; }
    }
    __syncthreads();
    if (tid < 64) rr[tid] = __expf(Ls[63] - Ls[tid]);

    // A matrix: thread -> (i = tid>>2, s in [(tid&3)*16, +16))
    {
        int i = tid >> 2, s0 = (tid & 3) * 16;
        float acc[16];
#pragma unroll
        for (int j = 0; j < 16; j++) acc[j] = 0.0f;
#pragma unroll
        for (int n = 0; n < 32; n++) {
            float qv = qs[i][n];
#pragma unroll
            for (int j = 0; j < 16; j++)
                acc[j] = fmaf(qv, ks[s0 + j][n], acc[j]);
        }
        float Li = Ls[i];
#pragma unroll
        for (int j = 0; j < 16; j++) {
            int s = s0 + j;
            As[i][s] = (s <= i) ? acc[j] * __expf(Li - Ls[s]) : 0.0f;
        }
        // qd -> global (smem qs untouched; safe)
        int cg = (tid & 3) * 8;
        float ei = __expf(Li);
        size_t gq = (e0 + (size_t)i * KK) * 32 + cg;
#pragma unroll
        for (int j = 0; j < 8; j++)
            g_qsel[gq + j] = qs[i][cg + j] * ei;
    }
    __syncthreads();

    // y_intra: thread -> (i = tid>>2, v in [(tid&3)*8, +8))
    {
        int i = tid >> 2, vg = (tid & 3) * 8;
        float y[8];
#pragma unroll
        for (int j = 0; j < 8; j++) y[j] = 0.0f;
#pragma unroll 4
        for (int s = 0; s < 64; s++) {
            float a = As[i][s];
#pragma unroll
            for (int j = 0; j < 8; j++)
                y[j] = fmaf(a, vs[s][vg + j], y[j]);
        }
        size_t gy = (e0 + (size_t)i * KK) * 32 + vg;
        *(float4*)&g_yslot[gy]     = make_float4(y[0], y[1], y[2], y[3]);
        *(float4*)&g_yslot[gy + 4] = make_float4(y[4], y[5], y[6], y[7]);
    }

    // U: thread -> (n = tid>>3, v in [(tid&7)*4, +4))
    {
        int n = tid >> 3, vg = (tid & 7) * 4;
        float u[4] = {0.f, 0.f, 0.f, 0.f};
#pragma unroll 4
        for (int s = 0; s < 64; s++) {
            float kd = ks[s][n] * rr[s];
#pragma unroll
            for (int j = 0; j < 4; j++)
                u[j] = fmaf(kd, vs[s][vg + j], u[j]);
        }
        *(float4*)&g_U[(size_t)cid * 1024 + n * 32 + vg] = make_float4(u[0], u[1], u[2], u[3]);
    }
    if (tid == 0) g_P63[cid] = __expf(Ls[63]);
}

// ---------------- kernel: chunked scan phase 2 (state propagation) ----------------
// Block per sequence (b,kk); 1024 threads = (n,v). 32 serial chunk steps.
__global__ void chunk_state(const float* __restrict__ S0,
                            float* __restrict__ sfin) {
    int tid = threadIdx.x;          // n*32+v
    int seq = blockIdx.x;           // b*KK+kk
    float S = S0[(size_t)seq * 1024 + tid];
#pragma unroll 1
    for (int c = 0; c < NCH; c++) {
        int cid = seq * NCH + c;
        g_Schunk[(size_t)cid * 1024 + tid] = S;
        float P = g_P63[cid];
        S = fmaf(P, S, g_U[(size_t)cid * 1024 + tid]);
    }
    if (sfin) sfin[(size_t)seq * 1024 + tid] = S;
}

// ---------------- kernel: chunked scan phase 3 (cross-chunk term) ----------------
// Block per chunk: y[i][v] += qd[i] . S_chunk[:,v]
__global__ void chunk_cross() {
    __shared__ float Sc[1024];
    __shared__ float qds[64][33];
    int tid = threadIdx.x;
    int cid = blockIdx.x;
    int b = cid >> 8, kk = (cid >> 5) & 7, c = cid & 31;
    size_t e0 = ((size_t)(b * TT + c * CC)) * KK + kk;

    {
        float4 s4 = *(const float4*)&g_Schunk[(size_t)cid * 1024 + tid * 4];
        *(float4*)&Sc[tid * 4] = s4;
    }
#pragma unroll
    for (int it = 0; it < 2; it++) {
        int i = (tid >> 3) + it * 32;
        int c4 = (tid & 7) * 4;
        float4 qv = *(const float4*)&g_qsel[(e0 + (size_t)i * KK) * 32 + c4];
        qds[i][c4] = qv.x; qds[i][c4+1] = qv.y; qds[i][c4+2] = qv.z; qds[i][c4+3] = qv.w;
    }
    __syncthreads();

    int i = tid >> 2, vg = (tid & 3) * 8;
    size_t gy = (e0 + (size_t)i * KK) * 32 + vg;
    float4 y0 = *(const float4*)&g_yslot[gy];
    float4 y1 = *(const float4*)&g_yslot[gy + 4];
    float y[8] = {y0.x, y0.y, y0.z, y0.w, y1.x, y1.y, y1.z, y1.w};
#pragma unroll 8
    for (int n = 0; n < 32; n++) {
        float qv = qds[i][n];
#pragma unroll
        for (int j = 0; j < 8; j++)
            y[j] = fmaf(qv, Sc[n * 32 + vg + j], y[j]);
    }
    *(float4*)&g_yslot[gy]     = make_float4(y[0], y[1], y[2], y[3]);
    *(float4*)&g_yslot[gy + 4] = make_float4(y[4], y[5], y[6], y[7]);
}

// ---------------- kernel: slot reduce + output projection ----------------
__global__ void outproj_kernel(float* __restrict__ out) {
    __shared__ float ysum[8][33];
    int tid = threadIdx.x;
    int tok0 = blockIdx.x * 8;
    {
        int tk = tid >> 5, v = tid & 31;
        float s = 0.0f;
        size_t p = (size_t)(tok0 + tk) * KK * 32 + v;
#pragma unroll
        for (int kk = 0; kk < KK; kk++) s += g_yslot[p + kk * 32];
        ysum[tk][v] = s;
    }
    __syncthreads();
    float acc[8][4];
#pragma unroll
    for (int tk = 0; tk < 8; tk++)
#pragma unroll
        for (int j = 0; j < 4; j++) acc[tk][j] = 0.0f;

#pragma unroll 4
    for (int vv = 0; vv < 32; vv++) {
        float w0 = g_WoT[vv * DD + tid];
        float w1 = g_WoT[vv * DD + tid + 256];
        float w2 = g_WoT[vv * DD + tid + 512];
        float w3 = g_WoT[vv * DD + tid + 768];
#pragma unroll
        for (int tk = 0; tk < 8; tk++) {
            float y = ysum[tk][vv];
            acc[tk][0] = fmaf(w0, y, acc[tk][0]);
            acc[tk][1] = fmaf(w1, y, acc[tk][1]);
            acc[tk][2] = fmaf(w2, y, acc[tk][2]);
            acc[tk][3] = fmaf(w3, y, acc[tk][3]);
        }
    }
#pragma unroll
    for (int tk = 0; tk < 8; tk++)
#pragma unroll
        for (int j = 0; j < 4; j++)
            out[(size_t)(tok0 + tk) * DD + j * 256 + tid] = acc[tk][j];
}

// ---------------- launch ----------------
extern "C" void kernel_launch(void* const* d_in, const int* in_sizes, int n_in,
                              void* d_out, int out_size) {
    const float* x       = (const float*)d_in[0];
    const float* Wr      = (const float*)d_in[1];
    const float* Wq      = (const float*)d_in[2];
    const float* Wk      = (const float*)d_in[3];
    const float* Wv      = (const float*)d_in[4];
    const float* Wa      = (const float*)d_in[5];
    const float* A_log   = (const float*)d_in[6];
    const float* dt_bias = (const float*)d_in[7];
    const float* Wo      = (const float*)d_in[8];
    const float* S0      = (const float*)d_in[9];
    float* out = (float*)d_out;

    const long y_elems = (long)NT * DD;
    const long s_elems = (long)BB * KK * NSd * HVd;
    float* sfin = ((long)out_size >= y_elems + s_elems) ? (out + y_elems) : nullptr;

    zero_counts<<<1, 64>>>();
    transpose_wo<<<128, 256>>>(Wo);
    gemm_ra_tc<<<NT / 64, 256>>>(x, Wr, Wa);
    route_kernel<<<NT / 8, 256>>>(A_log, dt_bias);
    prefix_kernel<<<1, 32>>>();
    scatter_kernel<<<NTS / 256, 256>>>();
    gemm_qkv_tc<<<dim3(MAXTILES, HH), 256>>>(x, Wq, Wk, Wv);
    chunk_intra<<<NCHUNKS, 256>>>();
    chunk_state<<<BB * KK, 1024>>>(S0, sfin);
    chunk_cross<<<NCHUNKS, 256>>>();
    outproj_kernel<<<NT / 8, 256>>>(out);
}

// round 5
// speedup vs baseline: 2.6866x; 1.4454x over previous
#include <cuda_runtime.h>
#include <cuda_bf16.h>
#include <math.h>

// Problem constants
#define BB   4
#define TT   2048
#define DD   1024
#define HH   64
#define NSd  32
#define KK   8
#define HVd  32
#define NT   8192      // BB*TT tokens
#define NTS  65536     // NT*KK token-slots
#define MAXTILES 64
#define CC   64        // chunk length
#define NCH  32        // chunks per sequence (TT/CC)
#define NCHUNKS 1024   // BB*KK*NCH

// ---------------- scratch (static device memory; no allocation) ----------------
__device__ float g_ra[NT * 128];
__device__ int   g_topi[NTS];
__device__ float g_rw[NTS];
__device__ float g_dsel[NTS];             // per-slot decay EXPONENT (<=0)
__device__ int   g_count[HH];
__device__ int   g_offset[HH];
__device__ int   g_cursor[HH];
__device__ int   g_list[NTS];
__device__ float g_qsel[NTS * 32];        // phase1 overwrites with qd = q*exp(L)
__device__ float g_ksel[NTS * 32];
__device__ float g_vsel[NTS * 32];
__device__ float g_yslot[NTS * 32];
__device__ float g_WoT[32 * DD];
__device__ float g_U[NCHUNKS * 1024];
__device__ float g_P63[NCHUNKS];
__device__ float g_Schunk[NCHUNKS * 1024];

// ---------------- helpers ----------------
__device__ __forceinline__ float silu_f(float x) {
    return x / (1.0f + expf(-x));
}

__device__ __forceinline__ void tf32_split(float x, unsigned& hi, unsigned& lo) {
    unsigned h;
    asm("cvt.rna.tf32.f32 %0, %1;" : "=r"(h) : "f"(x));
    float hf = __uint_as_float(h);
    float l = x - hf;
    unsigned lb;
    asm("cvt.rna.tf32.f32 %0, %1;" : "=r"(lb) : "f"(l));
    hi = h; lo = lb;
}

__device__ __forceinline__ void mma_tf32(float* c, const unsigned* a, const unsigned* b) {
    asm volatile(
        "mma.sync.aligned.m16n8k8.row.col.f32.tf32.tf32.f32 "
        "{%0,%1,%2,%3}, {%4,%5,%6,%7}, {%8,%9}, {%0,%1,%2,%3};"
        : "+f"(c[0]), "+f"(c[1]), "+f"(c[2]), "+f"(c[3])
        : "r"(a[0]), "r"(a[1]), "r"(a[2]), "r"(a[3]), "r"(b[0]), "r"(b[1]));
}

// bf16 error-compensated split of a pair of floats
__device__ __forceinline__ void bf16_split2(float x0, float x1, unsigned& hi, unsigned& lo) {
    __nv_bfloat162 h2 = __floats2bfloat162_rn(x0, x1);
    float h0 = __bfloat162float(__low2bfloat16(h2));
    float h1 = __bfloat162float(__high2bfloat16(h2));
    __nv_bfloat162 l2 = __floats2bfloat162_rn(x0 - h0, x1 - h1);
    hi = *(unsigned*)&h2;
    lo = *(unsigned*)&l2;
}

__device__ __forceinline__ void mma_bf16(float* c, const unsigned* a, const unsigned* b) {
    asm volatile(
        "mma.sync.aligned.m16n8k16.row.col.f32.bf16.bf16.f32 "
        "{%0,%1,%2,%3}, {%4,%5,%6,%7}, {%8,%9}, {%0,%1,%2,%3};"
        : "+f"(c[0]), "+f"(c[1]), "+f"(c[2]), "+f"(c[3])
        : "r"(a[0]), "r"(a[1]), "r"(a[2]), "r"(a[3]), "r"(b[0]), "r"(b[1]));
}

// ---------------- kernel: init (transpose Wo + zero counters) ----------------
__global__ void init_kernel(const float* __restrict__ Wo) {
    int o = blockIdx.x * 256 + threadIdx.x;
    int v = o >> 10, d = o & 1023;
    g_WoT[o] = Wo[d * 32 + v];
    if (o < HH) { g_count[o] = 0; g_cursor[o] = 0; }
}

// ---------------- kernel: router + decay GEMM (tf32 3-pass; precision-critical) ----------------
__global__ void gemm_ra_tc(const float* __restrict__ x,
                           const float* __restrict__ Wr,
                           const float* __restrict__ Wa) {
    __shared__ __align__(16) float sA[2 * 16 * 72];
    __shared__ __align__(16) float sW[2 * 16 * 136];
    float* Ahi = sA;            float* Alo = sA + 16 * 72;
    float* Whi = sW;            float* Wlo = sW + 16 * 136;

    int tid = threadIdx.x;
    int m0 = blockIdx.x * 64;
    int w = tid >> 5, lane = tid & 31;
    int mw = w >> 1, nw = w & 1;
    int g = lane >> 2, tig = lane & 3;

    float acc[8][4];
#pragma unroll
    for (int i = 0; i < 8; i++)
#pragma unroll
        for (int j = 0; j < 4; j++) acc[i][j] = 0.0f;

    int xr = tid >> 2;
    int xc = (tid & 3) * 4;

    for (int k0 = 0; k0 < DD; k0 += 16) {
        {
            const float4 p = *(const float4*)(x + (size_t)(m0 + xr) * DD + k0 + xc);
            float xv[4] = {p.x, p.y, p.z, p.w};
#pragma unroll
            for (int j = 0; j < 4; j++) {
                unsigned h_, l_; tf32_split(xv[j], h_, l_);
                Ahi[(xc + j) * 72 + xr] = __uint_as_float(h_);
                Alo[(xc + j) * 72 + xr] = __uint_as_float(l_);
            }
        }
#pragma unroll
        for (int it = 0; it < 2; it++) {
            int u = tid + it * 256;
            int r = u >> 2, c = (u & 3) * 4;
            const float* src = (r < 64) ? (Wr + (size_t)r * DD)
                                        : (Wa + (size_t)(r - 64) * DD);
            const float4 p = *(const float4*)(src + k0 + c);
            float wv[4] = {p.x, p.y, p.z, p.w};
#pragma unroll
            for (int j = 0; j < 4; j++) {
                unsigned h_, l_; tf32_split(wv[j], h_, l_);
                Whi[(c + j) * 136 + r] = __uint_as_float(h_);
                Wlo[(c + j) * 136 + r] = __uint_as_float(l_);
            }
        }
        __syncthreads();
#pragma unroll
        for (int ka = 0; ka < 2; ka++) {
            int kb = ka * 8;
            int row0 = mw * 16 + g;
            unsigned ahi[4], alo[4];
            ahi[0] = __float_as_uint(Ahi[(kb + tig) * 72 + row0]);
            ahi[1] = __float_as_uint(Ahi[(kb + tig) * 72 + row0 + 8]);
            ahi[2] = __float_as_uint(Ahi[(kb + tig + 4) * 72 + row0]);
            ahi[3] = __float_as_uint(Ahi[(kb + tig + 4) * 72 + row0 + 8]);
            alo[0] = __float_as_uint(Alo[(kb + tig) * 72 + row0]);
            alo[1] = __float_as_uint(Alo[(kb + tig) * 72 + row0 + 8]);
            alo[2] = __float_as_uint(Alo[(kb + tig + 4) * 72 + row0]);
            alo[3] = __float_as_uint(Alo[(kb + tig + 4) * 72 + row0 + 8]);
#pragma unroll
            for (int na = 0; na < 8; na++) {
                int col = nw * 64 + na * 8 + g;
                unsigned bhi[2], blo[2];
                bhi[0] = __float_as_uint(Whi[(kb + tig) * 136 + col]);
                bhi[1] = __float_as_uint(Whi[(kb + tig + 4) * 136 + col]);
                blo[0] = __float_as_uint(Wlo[(kb + tig) * 136 + col]);
                blo[1] = __float_as_uint(Wlo[(kb + tig + 4) * 136 + col]);
                mma_tf32(acc[na], ahi, bhi);
                mma_tf32(acc[na], ahi, blo);
                mma_tf32(acc[na], alo, bhi);
            }
        }
        __syncthreads();
    }
#pragma unroll
    for (int na = 0; na < 8; na++) {
        int col = nw * 64 + na * 8 + tig * 2;
        int row = m0 + mw * 16 + g;
        *(float2*)&g_ra[(size_t)row * 128 + col]       = make_float2(acc[na][0], acc[na][1]);
        *(float2*)&g_ra[(size_t)(row + 8) * 128 + col] = make_float2(acc[na][2], acc[na][3]);
    }
}

// ---------------- kernel: routing (top-8, rw, decay exponent); 2 tokens/warp ----------------
__global__ void route_kernel(const float* __restrict__ A_log,
                             const float* __restrict__ dt_bias) {
    int lane = threadIdx.x & 31;
    int w = threadIdx.x >> 5;
    int tok0 = blockIdx.x * 16 + w * 2;

    float v0[2], v1[2];
    const float* ra0 = g_ra + (size_t)tok0 * 128;
    const float* ra1 = ra0 + 128;
    v0[0] = ra0[lane]; v1[0] = ra0[lane + 32];
    v0[1] = ra1[lane]; v1[1] = ra1[lane + 32];
    int i0 = lane, i1 = lane + 32;
    float topv[2][8]; int tophi[2][8];
#pragma unroll
    for (int it = 0; it < 8; it++) {
#pragma unroll
        for (int tt = 0; tt < 2; tt++) {
            float bv; int bi;
            if (v0[tt] > v1[tt] || (v0[tt] == v1[tt] && i0 < i1)) { bv = v0[tt]; bi = i0; }
            else                                                   { bv = v1[tt]; bi = i1; }
#pragma unroll
            for (int off = 16; off > 0; off >>= 1) {
                float ov = __shfl_xor_sync(0xffffffffu, bv, off);
                int   oi = __shfl_xor_sync(0xffffffffu, bi, off);
                if (ov > bv || (ov == bv && oi < bi)) { bv = ov; bi = oi; }
            }
            topv[tt][it] = bv; tophi[tt][it] = bi;
            if (bi == i0) v0[tt] = -INFINITY;
            if (bi == i1) v1[tt] = -INFINITY;
        }
    }
#pragma unroll
    for (int tt = 0; tt < 2; tt++) {
        float s = 0.0f;
#pragma unroll
        for (int j = 0; j < 8; j++) s += expf(topv[tt][j] - topv[tt][0]);

        float myv = 0.0f; int myh = 0;
#pragma unroll
        for (int it = 0; it < 8; it++)
            if (lane == it) { myv = topv[tt][it]; myh = tophi[tt][it]; }

        if (lane < 8) {
            const float* ra = (tt == 0) ? ra0 : ra1;
            float rw = expf(myv - topv[tt][0]) / s;
            float z = ra[64 + myh] + dt_bias[myh];
            float sp = (z > 20.0f) ? z : log1pf(expf(z));
            int e = (tok0 + tt) * 8 + lane;
            g_topi[e] = myh;
            g_rw[e] = rw;
            g_dsel[e] = -expf(A_log[myh]) * sp;
            atomicAdd(&g_count[myh], 1);
        }
    }
}

// ---------------- kernel: prefix sum ----------------
__global__ void prefix_kernel() {
    if (threadIdx.x == 0) {
        int acc = 0;
        for (int h = 0; h < HH; h++) { g_offset[h] = acc; acc += g_count[h]; }
    }
}

// ---------------- kernel: scatter ----------------
__global__ void scatter_kernel() {
    int e = blockIdx.x * 256 + threadIdx.x;
    int h = g_topi[e];
    int pos = atomicAdd(&g_cursor[h], 1);
    g_list[g_offset[h] + pos] = e;
}

// ---------------- kernel: grouped q/k/v GEMM (bf16 3-pass, m16n8k16) ----------------
// C[64 tok][96] = Xg[64][1024] * [Wq_h;Wk_h;Wv_h]^T.  BM=64, BN=96, BK=32.
// SMEM: bf16 k-major tiles, row stride 40 bf16 (20 words) -> conflict-free frag loads.
__global__ void gemm_qkv_bf(const float* __restrict__ x,
                            const float* __restrict__ Wq,
                            const float* __restrict__ Wk,
                            const float* __restrict__ Wv) {
    __shared__ int s_ent[64];
    __shared__ __align__(16) unsigned char sraw[25600];
    unsigned* AhiW = (unsigned*)sraw;                  // 64*20 = 1280 words
    unsigned* AloW = (unsigned*)(sraw + 5120);
    unsigned* WhiW = (unsigned*)(sraw + 10240);        // 96*20 = 1920 words
    unsigned* WloW = (unsigned*)(sraw + 17920);
    float* Cs = (float*)sraw;                          // overlay [64][97] = 24832 B

    int tid = threadIdx.x;
    int h = blockIdx.y;
    int cnt = g_count[h];
    int t0 = blockIdx.x * 64;
    if (t0 >= cnt) return;
    int off = g_offset[h];
    if (tid < 64) s_ent[tid] = (t0 + tid < cnt) ? g_list[off + t0 + tid] : -1;
    __syncthreads();

    int w = tid >> 5, lane = tid & 31;
    int mw = w >> 1, nw = w & 1;
    int g = lane >> 2, tig = lane & 3;

    float acc[6][4];
#pragma unroll
    for (int i = 0; i < 6; i++)
#pragma unroll
        for (int j = 0; j < 4; j++) acc[i][j] = 0.0f;

    int xr = tid >> 2;            // 0..63
    int xc = (tid & 3) * 8;       // 0,8,16,24
    int e_my = s_ent[xr];
    const float* xrow = (e_my >= 0) ? (x + (size_t)(e_my >> 3) * DD + xc) : nullptr;

    for (int k0 = 0; k0 < DD; k0 += 32) {
        // gathered X tile 64x32 -> bf16 hi/lo
        {
            float xv[8] = {0.f,0.f,0.f,0.f,0.f,0.f,0.f,0.f};
            if (e_my >= 0) {
                const float4 p0 = *(const float4*)(xrow + k0);
                const float4 p1 = *(const float4*)(xrow + k0 + 4);
                xv[0]=p0.x; xv[1]=p0.y; xv[2]=p0.z; xv[3]=p0.w;
                xv[4]=p1.x; xv[5]=p1.y; xv[6]=p1.z; xv[7]=p1.w;
            }
#pragma unroll
            for (int j = 0; j < 8; j += 2) {
                unsigned h_, l_; bf16_split2(xv[j], xv[j+1], h_, l_);
                int wd = xr * 20 + ((xc + j) >> 1);
                AhiW[wd] = h_; AloW[wd] = l_;
            }
        }
        // W tile 96x32 -> bf16 hi/lo (384 units of 8 floats)
#pragma unroll
        for (int it = 0; it < 2; it++) {
            int u = tid + it * 256;
            if (u < 384) {
                int r = u >> 2, c = (u & 3) * 8;
                const float* src = (r < 32) ? (Wq + (size_t)(h * 32 + r) * DD)
                                 : (r < 64) ? (Wk + (size_t)(h * 32 + r - 32) * DD)
                                            : (Wv + (size_t)(h * 32 + r - 64) * DD);
                const float4 p0 = *(const float4*)(src + k0 + c);
                const float4 p1 = *(const float4*)(src + k0 + c + 4);
                float wv[8] = {p0.x, p0.y, p0.z, p0.w, p1.x, p1.y, p1.z, p1.w};
#pragma unroll
                for (int j = 0; j < 8; j += 2) {
                    unsigned h_, l_; bf16_split2(wv[j], wv[j+1], h_, l_);
                    int wd = r * 20 + ((c + j) >> 1);
                    WhiW[wd] = h_; WloW[wd] = l_;
                }
            }
        }
        __syncthreads();
#pragma unroll
        for (int ka = 0; ka < 2; ka++) {
            int kw = ka * 8 + tig;          // word offset within row
            int r0 = mw * 16 + g;
            unsigned ahi[4], alo[4];
            ahi[0] = AhiW[r0 * 20 + kw];
            ahi[1] = AhiW[(r0 + 8) * 20 + kw];
            ahi[2] = AhiW[r0 * 20 + kw + 4];
            ahi[3] = AhiW[(r0 + 8) * 20 + kw + 4];
            alo[0] = AloW[r0 * 20 + kw];
            alo[1] = AloW[(r0 + 8) * 20 + kw];
            alo[2] = AloW[r0 * 20 + kw + 4];
            alo[3] = AloW[(r0 + 8) * 20 + kw + 4];
#pragma unroll
            for (int na = 0; na < 6; na++) {
                int col = nw * 48 + na * 8 + g;
                unsigned bhi[2], blo[2];
                bhi[0] = WhiW[col * 20 + kw];
                bhi[1] = WhiW[col * 20 + kw + 4];
                blo[0] = WloW[col * 20 + kw];
                blo[1] = WloW[col * 20 + kw + 4];
                mma_bf16(acc[na], ahi, bhi);
                mma_bf16(acc[na], ahi, blo);
                mma_bf16(acc[na], alo, bhi);
            }
        }
        __syncthreads();
    }

    // stage accumulators into Cs overlay
#pragma unroll
    for (int na = 0; na < 6; na++) {
        int col = nw * 48 + na * 8 + tig * 2;
        int row = mw * 16 + g;
        Cs[row * 97 + col]           = acc[na][0];
        Cs[row * 97 + col + 1]       = acc[na][1];
        Cs[(row + 8) * 97 + col]     = acc[na][2];
        Cs[(row + 8) * 97 + col + 1] = acc[na][3];
    }
    __syncthreads();

#pragma unroll 1
    for (int rep = 0; rep < 8; rep++) {
        int r = rep * 8 + w;
        int e = s_ent[r];
        if (e < 0) continue;
        float wr = g_rw[e];
        float qv = Cs[r * 97 + lane];
        float qs = silu_f(qv);
        float ssq = qs * qs;
#pragma unroll
        for (int o = 16; o > 0; o >>= 1) ssq += __shfl_xor_sync(0xffffffffu, ssq, o);
        g_qsel[(size_t)e * 32 + lane] = qs * rsqrtf(ssq + 1e-6f) * wr;
        float kv = Cs[r * 97 + 32 + lane];
        float ks = silu_f(kv);
        float ssk = ks * ks;
#pragma unroll
        for (int o = 16; o > 0; o >>= 1) ssk += __shfl_xor_sync(0xffffffffu, ssk, o);
        g_ksel[(size_t)e * 32 + lane] = ks * rsqrtf(ssk + 1e-6f);
        float vv = Cs[r * 97 + 64 + lane];
        g_vsel[(size_t)e * 32 + lane] = silu_f(vv);
    }
}

// ---------------- kernel: chunked scan phase 1 (intra-chunk) ----------------
__global__ void chunk_intra() {
    __shared__ float qs[64][33], ks[64][33], vs[64][33];
    __shared__ float As[64][65];
    __shared__ float Ls[64], rr[64];
    int tid = threadIdx.x;
    int cid = blockIdx.x;
    int b = cid >> 8, kk = (cid >> 5) & 7, c = cid & 31;
    size_t e0 = ((size_t)(b * TT + c * CC)) * KK + kk;

#pragma unroll
    for (int it = 0; it < 2; it++) {
        int i = (tid >> 3) + it * 32;
        int c4 = (tid & 7) * 4;
        size_t gidx = (e0 + (size_t)i * KK) * 32 + c4;
        float4 qv = *(const float4*)&g_qsel[gidx];
        float4 kv = *(const float4*)&g_ksel[gidx];
        float4 vv = *(const float4*)&g_vsel[gidx];
        qs[i][c4] = qv.x; qs[i][c4+1] = qv.y; qs[i][c4+2] = qv.z; qs[i][c4+3] = qv.w;
        ks[i][c4] = kv.x; ks[i][c4+1] = kv.y; ks[i][c4+2] = kv.z; ks[i][c4+3] = kv.w;
        vs[i][c4] = vv.x; vs[i][c4+1] = vv.y; vs[i][c4+2] = vv.z; vs[i][c4+3] = vv.w;
    }
    if (tid < 64) Ls[tid] = g_dsel[e0 + (size_t)tid * KK];
    __syncthreads();
    if (tid == 0) {
        float a = 0.0f;
        for (int i = 0; i < 64; i++) { a += Ls[i]; Ls[i] = a; }
    }
    __syncthreads();
    if (tid < 64) rr[tid] = __expf(Ls[63] - Ls[tid]);

    {
        int i = tid >> 2, s0 = (tid & 3) * 16;
        float acc[16];
#pragma unroll
        for (int j = 0; j < 16; j++) acc[j] = 0.0f;
#pragma unroll
        for (int n = 0; n < 32; n++) {
            float qv = qs[i][n];
#pragma unroll
            for (int j = 0; j < 16; j++)
                acc[j] = fmaf(qv, ks[s0 + j][n], acc[j]);
        }
        float Li = Ls[i];
#pragma unroll
        for (int j = 0; j < 16; j++) {
            int s = s0 + j;
            As[i][s] = (s <= i) ? acc[j] * __expf(Li - Ls[s]) : 0.0f;
        }
        int cg = (tid & 3) * 8;
        float ei = __expf(Li);
        size_t gq = (e0 + (size_t)i * KK) * 32 + cg;
#pragma unroll
        for (int j = 0; j < 8; j++)
            g_qsel[gq + j] = qs[i][cg + j] * ei;
    }
    __syncthreads();

    {
        int i = tid >> 2, vg = (tid & 3) * 8;
        float y[8];
#pragma unroll
        for (int j = 0; j < 8; j++) y[j] = 0.0f;
#pragma unroll 4
        for (int s = 0; s < 64; s++) {
            float a = As[i][s];
#pragma unroll
            for (int j = 0; j < 8; j++)
                y[j] = fmaf(a, vs[s][vg + j], y[j]);
        }
        size_t gy = (e0 + (size_t)i * KK) * 32 + vg;
        *(float4*)&g_yslot[gy]     = make_float4(y[0], y[1], y[2], y[3]);
        *(float4*)&g_yslot[gy + 4] = make_float4(y[4], y[5], y[6], y[7]);
    }

    {
        int n = tid >> 3, vg = (tid & 7) * 4;
        float u[4] = {0.f, 0.f, 0.f, 0.f};
#pragma unroll 4
        for (int s = 0; s < 64; s++) {
            float kd = ks[s][n] * rr[s];
#pragma unroll
            for (int j = 0; j < 4; j++)
                u[j] = fmaf(kd, vs[s][vg + j], u[j]);
        }
        *(float4*)&g_U[(size_t)cid * 1024 + n * 32 + vg] = make_float4(u[0], u[1], u[2], u[3]);
    }
    if (tid == 0) g_P63[cid] = __expf(Ls[63]);
}

// ---------------- kernel: chunked scan phase 2 (state propagation) ----------------
__global__ void chunk_state(const float* __restrict__ S0,
                            float* __restrict__ sfin) {
    int tid = threadIdx.x;
    int seq = blockIdx.x;
    float S = S0[(size_t)seq * 1024 + tid];
#pragma unroll 1
    for (int c = 0; c < NCH; c++) {
        int cid = seq * NCH + c;
        g_Schunk[(size_t)cid * 1024 + tid] = S;
        float P = g_P63[cid];
        S = fmaf(P, S, g_U[(size_t)cid * 1024 + tid]);
    }
    if (sfin) sfin[(size_t)seq * 1024 + tid] = S;
}

// ---------------- kernel: chunked scan phase 3 (cross-chunk term) ----------------
__global__ void chunk_cross() {
    __shared__ float Sc[1024];
    __shared__ float qds[64][33];
    int tid = threadIdx.x;
    int cid = blockIdx.x;
    int b = cid >> 8, kk = (cid >> 5) & 7, c = cid & 31;
    size_t e0 = ((size_t)(b * TT + c * CC)) * KK + kk;

    {
        float4 s4 = *(const float4*)&g_Schunk[(size_t)cid * 1024 + tid * 4];
        *(float4*)&Sc[tid * 4] = s4;
    }
#pragma unroll
    for (int it = 0; it < 2; it++) {
        int i = (tid >> 3) + it * 32;
        int c4 = (tid & 7) * 4;
        float4 qv = *(const float4*)&g_qsel[(e0 + (size_t)i * KK) * 32 + c4];
        qds[i][c4] = qv.x; qds[i][c4+1] = qv.y; qds[i][c4+2] = qv.z; qds[i][c4+3] = qv.w;
    }
    __syncthreads();

    int i = tid >> 2, vg = (tid & 3) * 8;
    size_t gy = (e0 + (size_t)i * KK) * 32 + vg;
    float4 y0 = *(const float4*)&g_yslot[gy];
    float4 y1 = *(const float4*)&g_yslot[gy + 4];
    float y[8] = {y0.x, y0.y, y0.z, y0.w, y1.x, y1.y, y1.z, y1.w};
#pragma unroll 8
    for (int n = 0; n < 32; n++) {
        float qv = qds[i][n];
#pragma unroll
        for (int j = 0; j < 8; j++)
            y[j] = fmaf(qv, Sc[n * 32 + vg + j], y[j]);
    }
    *(float4*)&g_yslot[gy]     = make_float4(y[0], y[1], y[2], y[3]);
    *(float4*)&g_yslot[gy + 4] = make_float4(y[4], y[5], y[6], y[7]);
}

// ---------------- kernel: slot reduce + output projection ----------------
__global__ void outproj_kernel(float* __restrict__ out) {
    __shared__ float ysum[8][33];
    int tid = threadIdx.x;
    int tok0 = blockIdx.x * 8;
    {
        int tk = tid >> 5, v = tid & 31;
        float s = 0.0f;
        size_t p = (size_t)(tok0 + tk) * KK * 32 + v;
#pragma unroll
        for (int kk = 0; kk < KK; kk++) s += g_yslot[p + kk * 32];
        ysum[tk][v] = s;
    }
    __syncthreads();
    float acc[8][4];
#pragma unroll
    for (int tk = 0; tk < 8; tk++)
#pragma unroll
        for (int j = 0; j < 4; j++) acc[tk][j] = 0.0f;

#pragma unroll 4
    for (int vv = 0; vv < 32; vv++) {
        float w0 = g_WoT[vv * DD + tid];
        float w1 = g_WoT[vv * DD + tid + 256];
        float w2 = g_WoT[vv * DD + tid + 512];
        float w3 = g_WoT[vv * DD + tid + 768];
#pragma unroll
        for (int tk = 0; tk < 8; tk++) {
            float y = ysum[tk][vv];
            acc[tk][0] = fmaf(w0, y, acc[tk][0]);
            acc[tk][1] = fmaf(w1, y, acc[tk][1]);
            acc[tk][2] = fmaf(w2, y, acc[tk][2]);
            acc[tk][3] = fmaf(w3, y, acc[tk][3]);
        }
    }
#pragma unroll
    for (int tk = 0; tk < 8; tk++)
#pragma unroll
        for (int j = 0; j < 4; j++)
            out[(size_t)(tok0 + tk) * DD + j * 256 + tid] = acc[tk][j];
}

// ---------------- launch ----------------
extern "C" void kernel_launch(void* const* d_in, const int* in_sizes, int n_in,
                              void* d_out, int out_size) {
    const float* x       = (const float*)d_in[0];
    const float* Wr      = (const float*)d_in[1];
    const float* Wq      = (const float*)d_in[2];
    const float* Wk      = (const float*)d_in[3];
    const float* Wv      = (const float*)d_in[4];
    const float* Wa      = (const float*)d_in[5];
    const float* A_log   = (const float*)d_in[6];
    const float* dt_bias = (const float*)d_in[7];
    const float* Wo      = (const float*)d_in[8];
    const float* S0      = (const float*)d_in[9];
    float* out = (float*)d_out;

    const long y_elems = (long)NT * DD;
    const long s_elems = (long)BB * KK * NSd * HVd;
    float* sfin = ((long)out_size >= y_elems + s_elems) ? (out + y_elems) : nullptr;

    init_kernel<<<128, 256>>>(Wo);
    gemm_ra_tc<<<NT / 64, 256>>>(x, Wr, Wa);
    route_kernel<<<NT / 16, 256>>>(A_log, dt_bias);
    prefix_kernel<<<1, 32>>>();
    scatter_kernel<<<NTS / 256, 256>>>();
    gemm_qkv_bf<<<dim3(MAXTILES, HH), 256>>>(x, Wq, Wk, Wv);
    chunk_intra<<<NCHUNKS, 256>>>();
    chunk_state<<<BB * KK, 1024>>>(S0, sfin);
    chunk_cross<<<NCHUNKS, 256>>>();
    outproj_kernel<<<NT / 8, 256>>>(out);
}